// round 5
// baseline (speedup 1.0000x reference)
#include <cuda_runtime.h>

#define NROWS   16384
#define INC     512
#define NG      64
#define NF      24
#define NO      16
#define ACCC    3584
#define RT      16
#define NTHR    512
#define SMEM_BYTES (ACCC * RT * 4)   // 229376

typedef unsigned long long u64;

static __device__ __forceinline__ u64 pk2(float a, float b) {
    u64 r;
    asm("mov.b64 %0, {%1, %2};" : "=l"(r) : "f"(a), "f"(b));
    return r;
}
static __device__ __forceinline__ void up2(u64 v, float &a, float &b) {
    asm("mov.b64 {%0, %1}, %2;" : "=f"(a), "=f"(b) : "l"(v));
}
static __device__ __forceinline__ u64 fma2(u64 a, u64 b, u64 c) {
    u64 d;
    asm("fma.rn.f32x2 %0, %1, %2, %3;" : "=l"(d) : "l"(a), "l"(b), "l"(c));
    return d;
}
// HW tanh: single MUFU op, ~2^-11 rel err (budgeted against the 1e-3 gate)
static __device__ __forceinline__ float tanhhw(float x) {
    float y;
    asm("tanh.approx.f32 %0, %1;" : "=f"(y) : "f"(x));
    return y;
}

// SMEM: plain [col][16 rows] fp32, col stride 64B.
// Thread = (g, op): group g, output pair o = {2op, 2op+1}, ALL 16 rows.
// acc[rp][j]: f32x2 over row-pair rp (rows 2rp, 2rp+1) for o-half j.
static __device__ __forceinline__ void glayer(float* sh, int g, int op,
                                              const float* __restrict__ W,
                                              const float* __restrict__ bia,
                                              const int* __restrict__ idx,
                                              int colbase)
{
    // Preload the 24 gather indices into registers
    int cols[NF];
    const int4* ip = reinterpret_cast<const int4*>(idx + g * NF);
    #pragma unroll
    for (int i = 0; i < NF / 4; i++) {
        int4 v = __ldg(&ip[i]);
        cols[4 * i + 0] = v.x; cols[4 * i + 1] = v.y;
        cols[4 * i + 2] = v.z; cols[4 * i + 3] = v.w;
    }

    u64 acc[8][2];
    {
        float2 bb = __ldg(reinterpret_cast<const float2*>(bia + g * NO + 2 * op));
        u64 b0 = pk2(bb.x, bb.x);
        u64 b1 = pk2(bb.y, bb.y);
        #pragma unroll
        for (int rp = 0; rp < 8; rp++) { acc[rp][0] = b0; acc[rp][1] = b1; }
    }

    const float2* wb = reinterpret_cast<const float2*>(W) + (size_t)g * NF * 8 + op;

    #pragma unroll
    for (int f = 0; f < NF; f++) {
        const float* col = sh + cols[f] * 16;
        ulonglong2 A0 = *reinterpret_cast<const ulonglong2*>(col + 0);   // rows 0-3
        ulonglong2 A1 = *reinterpret_cast<const ulonglong2*>(col + 4);   // rows 4-7
        ulonglong2 A2 = *reinterpret_cast<const ulonglong2*>(col + 8);   // rows 8-11
        ulonglong2 A3 = *reinterpret_cast<const ulonglong2*>(col + 12);  // rows 12-15
        float2 w = __ldg(wb + f * 8);
        u64 w0 = pk2(w.x, w.x);
        u64 w1 = pk2(w.y, w.y);
        acc[0][0] = fma2(A0.x, w0, acc[0][0]); acc[0][1] = fma2(A0.x, w1, acc[0][1]);
        acc[1][0] = fma2(A0.y, w0, acc[1][0]); acc[1][1] = fma2(A0.y, w1, acc[1][1]);
        acc[2][0] = fma2(A1.x, w0, acc[2][0]); acc[2][1] = fma2(A1.x, w1, acc[2][1]);
        acc[3][0] = fma2(A1.y, w0, acc[3][0]); acc[3][1] = fma2(A1.y, w1, acc[3][1]);
        acc[4][0] = fma2(A2.x, w0, acc[4][0]); acc[4][1] = fma2(A2.x, w1, acc[4][1]);
        acc[5][0] = fma2(A2.y, w0, acc[5][0]); acc[5][1] = fma2(A2.y, w1, acc[5][1]);
        acc[6][0] = fma2(A3.x, w0, acc[6][0]); acc[6][1] = fma2(A3.x, w1, acc[6][1]);
        acc[7][0] = fma2(A3.y, w0, acc[7][0]); acc[7][1] = fma2(A3.y, w1, acc[7][1]);
    }

    // tanh + writeback: 2 columns x 16 rows
    float v[2][16];
    #pragma unroll
    for (int rp = 0; rp < 8; rp++) {
        up2(acc[rp][0], v[0][2 * rp], v[0][2 * rp + 1]);
        up2(acc[rp][1], v[1][2 * rp], v[1][2 * rp + 1]);
    }
    #pragma unroll
    for (int j = 0; j < 2; j++)
        #pragma unroll
        for (int r = 0; r < 16; r++)
            v[j][r] = tanhhw(v[j][r]);

    #pragma unroll
    for (int j = 0; j < 2; j++) {
        float* cp = sh + (colbase + g * NO + 2 * op + j) * 16;
        #pragma unroll
        for (int k = 0; k < 4; k++)
            *reinterpret_cast<float4*>(cp + k * 4) =
                make_float4(v[j][4 * k], v[j][4 * k + 1], v[j][4 * k + 2], v[j][4 * k + 3]);
    }
}

__global__ void __launch_bounds__(NTHR, 1)
model_kernel(const float* __restrict__ x,
             const float* __restrict__ W1, const float* __restrict__ b1,
             const float* __restrict__ W2, const float* __restrict__ b2,
             const float* __restrict__ W3, const float* __restrict__ b3,
             const float* __restrict__ Wo, const float* __restrict__ bo,
             const int* __restrict__ idx1, const int* __restrict__ idx2,
             const int* __restrict__ idx3, const int* __restrict__ idxo,
             float* __restrict__ out)
{
    extern __shared__ float sh[];  // [ACCC][16] plain column-major tile
    const int t = threadIdx.x;
    const int rowbase = blockIdx.x * RT;

    // ---- Stage x tile (16 rows x 512 cols), transposed into SMEM ----
    // thread = (col, chunk): loads 4 rows of one column (32B-sector aligned
    // across the warp: 8 cols x 4 rows = 4 full sectors), stores STS.128
    // conflict-free (warp covers 512B contiguous SMEM).
    {
        const int k  = t & 3;        // row chunk 0..3 (rows 4k..4k+3)
        const int cb = t >> 2;       // col 0..127 (+ 128*it)
        const float* xb = x + (size_t)rowbase * INC;
        #pragma unroll
        for (int it = 0; it < 4; it++) {
            int c = cb + it * 128;
            float v0 = __ldg(&xb[(4 * k + 0) * INC + c]);
            float v1 = __ldg(&xb[(4 * k + 1) * INC + c]);
            float v2 = __ldg(&xb[(4 * k + 2) * INC + c]);
            float v3 = __ldg(&xb[(4 * k + 3) * INC + c]);
            *reinterpret_cast<float4*>(sh + c * 16 + k * 4) =
                make_float4(v0, v1, v2, v3);
        }
    }
    __syncthreads();

    const int g  = t >> 3;   // group 0..63
    const int op = t & 7;    // o-pair 0..7

    glayer(sh, g, op, W1, b1, idx1, 512);
    __syncthreads();
    glayer(sh, g, op, W2, b2, idx2, 1536);
    __syncthreads();
    glayer(sh, g, op, W3, b3, idx3, 2560);
    __syncthreads();

    // ---- Output layer: 4 groups x 48 f x 16 o, linear ----
    {
        int ot = t & 15;
        int og = (t >> 4) & 3;
        int oq = t >> 6;                    // row pair 0..7
        float bias = __ldg(&bo[og * 16 + ot]);
        float h0 = bias, h1 = bias;
        const int* gi = idxo + og * 48;
        const float* w = Wo + og * 48 * 16 + ot;
        #pragma unroll
        for (int f = 0; f < 48; f++) {
            int c = __ldg(&gi[f]);
            float2 a2 = *reinterpret_cast<const float2*>(sh + c * 16 + oq * 2);
            float wf = __ldg(&w[f * 16]);
            h0 = fmaf(a2.x, wf, h0);
            h1 = fmaf(a2.y, wf, h1);
        }
        float* ob = out + (size_t)(rowbase + oq * 2) * 64 + og * 16 + ot;
        ob[0]  = h0;
        ob[64] = h1;
    }
}

extern "C" void kernel_launch(void* const* d_in, const int* in_sizes, int n_in,
                              void* d_out, int out_size)
{
    const float* x   = (const float*)d_in[0];
    const float* W1  = (const float*)d_in[1];
    const float* b1  = (const float*)d_in[2];
    const float* W2  = (const float*)d_in[3];
    const float* b2  = (const float*)d_in[4];
    const float* W3  = (const float*)d_in[5];
    const float* b3  = (const float*)d_in[6];
    const float* Wo  = (const float*)d_in[7];
    const float* bo  = (const float*)d_in[8];
    const int*   i1  = (const int*)d_in[9];
    const int*   i2  = (const int*)d_in[10];
    const int*   i3  = (const int*)d_in[11];
    const int*   io  = (const int*)d_in[12];
    float*       out = (float*)d_out;

    cudaFuncSetAttribute(model_kernel,
                         cudaFuncAttributeMaxDynamicSharedMemorySize, SMEM_BYTES);
    model_kernel<<<NROWS / RT, NTHR, SMEM_BYTES>>>(
        x, W1, b1, W2, b2, W3, b3, Wo, bo, i1, i2, i3, io, out);
}

// round 6
// speedup vs baseline: 1.6057x; 1.6057x over previous
#include <cuda_runtime.h>
#include <cuda_fp16.h>

#define NROWS   16384
#define INC     512
#define NG      64
#define NF      24
#define NO      16
#define ACCC    3584
#define RT      32
#define NTHR    512
#define SMEM_BYTES (ACCC * RT * 2)   // 229376 bytes (fp16)

typedef unsigned long long u64;

static __device__ __forceinline__ u64 pk2(float a, float b) {
    u64 r;
    asm("mov.b64 %0, {%1, %2};" : "=l"(r) : "f"(a), "f"(b));
    return r;
}
static __device__ __forceinline__ void up2(u64 v, float &a, float &b) {
    asm("mov.b64 {%0, %1}, %2;" : "=f"(a), "=f"(b) : "l"(v));
}
static __device__ __forceinline__ u64 fma2(u64 a, u64 b, u64 c) {
    u64 d;
    asm("fma.rn.f32x2 %0, %1, %2, %3;" : "=l"(d) : "l"(a), "l"(b), "l"(c));
    return d;
}
static __device__ __forceinline__ float tanhhw(float x) {
    float y;
    asm("tanh.approx.f32 %0, %1;" : "=f"(y) : "f"(x));
    return y;
}

// fp16 tile: element (col c, row r) lives in 8B chunk j=r/4.
// Physical chunk slot = j ^ ((c ^ (c>>3)) & 7)  -> spreads banks for random
// gathers AND for the sequential-column writeback (col bits >=3 participate).
#define CHASH(c)   ((((c) ^ ((c) >> 3)) & 7))

static __device__ __forceinline__ const __half* colptr(const __half* sh, int c, int j) {
    return sh + c * RT + ((j ^ CHASH(c)) << 2);
}
static __device__ __forceinline__ __half* colptrw(__half* sh, int c, int j) {
    return sh + c * RT + ((j ^ CHASH(c)) << 2);
}

// Load 4 rows (one chunk) of column c as 4 floats
static __device__ __forceinline__ void load4(const __half* sh, int c, int j,
                                             float &a0, float &a1, float &a2, float &a3) {
    uint2 raw = *reinterpret_cast<const uint2*>(colptr(sh, c, j));
    __half2 h01 = reinterpret_cast<__half2&>(raw.x);
    __half2 h23 = reinterpret_cast<__half2&>(raw.y);
    float2 f01 = __half22float2(h01);
    float2 f23 = __half22float2(h23);
    a0 = f01.x; a1 = f01.y; a2 = f23.x; a3 = f23.y;
}
static __device__ __forceinline__ void store4(__half* sh, int c, int j,
                                              float v0, float v1, float v2, float v3) {
    __half2 ha = __floats2half2_rn(v0, v1);
    __half2 hb = __floats2half2_rn(v2, v3);
    uint2 st;
    st.x = reinterpret_cast<unsigned&>(ha);
    st.y = reinterpret_cast<unsigned&>(hb);
    *reinterpret_cast<uint2*>(colptrw(sh, c, j)) = st;
}

// Thread = (g, q): group g, row-quad q (rows 4q..4q+3), all 16 outputs.
// acc[r][op] = f32x2 over outputs (2op, 2op+1) for local row r.
static __device__ __forceinline__ void glayer(__half* sh, int g, int q,
                                              const float* __restrict__ W,
                                              const float* __restrict__ bia,
                                              const int* __restrict__ idx,
                                              int colbase)
{
    u64 acc[4][8];
    {
        const float2* b2 = reinterpret_cast<const float2*>(bia + g * NO);
        #pragma unroll
        for (int op = 0; op < 8; op++) {
            float2 bb = __ldg(&b2[op]);
            u64 bv = pk2(bb.x, bb.y);
            acc[0][op] = bv; acc[1][op] = bv; acc[2][op] = bv; acc[3][op] = bv;
        }
    }
    const ulonglong2* wb = reinterpret_cast<const ulonglong2*>(W + (size_t)g * NF * NO);
    const int4* ip = reinterpret_cast<const int4*>(idx + g * NF);

    #pragma unroll
    for (int half = 0; half < 2; half++) {
        int cols[12];
        #pragma unroll
        for (int i = 0; i < 3; i++) {
            int4 v = __ldg(&ip[half * 3 + i]);
            cols[4 * i + 0] = v.x; cols[4 * i + 1] = v.y;
            cols[4 * i + 2] = v.z; cols[4 * i + 3] = v.w;
        }
        #pragma unroll
        for (int ff = 0; ff < 12; ff++) {
            int f = half * 12 + ff;
            int c = cols[ff];
            float a0, a1, a2, a3;
            load4(sh, c, q, a0, a1, a2, a3);
            u64 d0 = pk2(a0, a0), d1 = pk2(a1, a1), d2 = pk2(a2, a2), d3 = pk2(a3, a3);
            ulonglong2 u0 = __ldg(&wb[f * 4 + 0]);
            ulonglong2 u1 = __ldg(&wb[f * 4 + 1]);
            ulonglong2 u2 = __ldg(&wb[f * 4 + 2]);
            ulonglong2 u3 = __ldg(&wb[f * 4 + 3]);
            u64 wp[8] = {u0.x, u0.y, u1.x, u1.y, u2.x, u2.y, u3.x, u3.y};
            #pragma unroll
            for (int op = 0; op < 8; op++) {
                acc[0][op] = fma2(d0, wp[op], acc[0][op]);
                acc[1][op] = fma2(d1, wp[op], acc[1][op]);
                acc[2][op] = fma2(d2, wp[op], acc[2][op]);
                acc[3][op] = fma2(d3, wp[op], acc[3][op]);
            }
        }
    }

    // tanh + fp16 writeback: 16 cols x 4 rows
    float v[4][NO];
    #pragma unroll
    for (int r = 0; r < 4; r++)
        #pragma unroll
        for (int op = 0; op < 8; op++)
            up2(acc[r][op], v[r][2 * op], v[r][2 * op + 1]);
    #pragma unroll
    for (int r = 0; r < 4; r++)
        #pragma unroll
        for (int o = 0; o < NO; o++)
            v[r][o] = tanhhw(v[r][o]);
    #pragma unroll
    for (int o = 0; o < NO; o++) {
        int c = colbase + g * NO + o;
        store4(sh, c, q, v[0][o], v[1][o], v[2][o], v[3][o]);
    }
}

__global__ void __launch_bounds__(NTHR, 1)
model_kernel(const float* __restrict__ x,
             const float* __restrict__ W1, const float* __restrict__ b1,
             const float* __restrict__ W2, const float* __restrict__ b2,
             const float* __restrict__ W3, const float* __restrict__ b3,
             const float* __restrict__ Wo, const float* __restrict__ bo,
             const int* __restrict__ idx1, const int* __restrict__ idx2,
             const int* __restrict__ idx3, const int* __restrict__ idxo,
             float* __restrict__ out)
{
    extern __shared__ __half sh[];  // [ACCC][32 rows] fp16, chunk-hash swizzle
    const int t = threadIdx.x;
    const int rowbase = blockIdx.x * RT;

    // ---- Stage x tile (32 rows x 512 cols) fp32->fp16 into SMEM ----
    // Iteration it handles row-chunk it; thread t handles column t.
    // LDG.32 coalesced across lanes (consecutive cols), STS.64 hash-spread.
    {
        const float* xb = x + (size_t)rowbase * INC;
        const int c = t;
        #pragma unroll
        for (int it = 0; it < 8; it++) {
            float v0 = __ldg(&xb[(4 * it + 0) * INC + c]);
            float v1 = __ldg(&xb[(4 * it + 1) * INC + c]);
            float v2 = __ldg(&xb[(4 * it + 2) * INC + c]);
            float v3 = __ldg(&xb[(4 * it + 3) * INC + c]);
            store4(sh, c, it, v0, v1, v2, v3);
        }
    }
    __syncthreads();

    const int g = t >> 3;   // group 0..63
    const int q = t & 7;    // row-quad 0..7

    glayer(sh, g, q, W1, b1, idx1, 512);
    __syncthreads();
    glayer(sh, g, q, W2, b2, idx2, 1536);
    __syncthreads();
    glayer(sh, g, q, W3, b3, idx3, 2560);
    __syncthreads();

    // ---- Output layer: 4 groups x 48 f x 16 o, linear, fp32 out ----
    {
        int ot = t & 15;
        int og = (t >> 4) & 3;
        int rq = t >> 6;                    // row-quad 0..7
        float bias = __ldg(&bo[og * 16 + ot]);
        float h0 = bias, h1 = bias, h2 = bias, h3 = bias;
        const int* gi = idxo + og * 48;
        const float* w = Wo + og * 48 * 16 + ot;
        #pragma unroll
        for (int f = 0; f < 48; f++) {
            int c = __ldg(&gi[f]);
            float a0, a1, a2, a3;
            load4(sh, c, rq, a0, a1, a2, a3);
            float wf = __ldg(&w[f * 16]);
            h0 = fmaf(a0, wf, h0);
            h1 = fmaf(a1, wf, h1);
            h2 = fmaf(a2, wf, h2);
            h3 = fmaf(a3, wf, h3);
        }
        float* ob = out + (size_t)(rowbase + rq * 4) * 64 + og * 16 + ot;
        ob[0]   = h0;
        ob[64]  = h1;
        ob[128] = h2;
        ob[192] = h3;
    }
}

extern "C" void kernel_launch(void* const* d_in, const int* in_sizes, int n_in,
                              void* d_out, int out_size)
{
    const float* x   = (const float*)d_in[0];
    const float* W1  = (const float*)d_in[1];
    const float* b1  = (const float*)d_in[2];
    const float* W2  = (const float*)d_in[3];
    const float* b2  = (const float*)d_in[4];
    const float* W3  = (const float*)d_in[5];
    const float* b3  = (const float*)d_in[6];
    const float* Wo  = (const float*)d_in[7];
    const float* bo  = (const float*)d_in[8];
    const int*   i1  = (const int*)d_in[9];
    const int*   i2  = (const int*)d_in[10];
    const int*   i3  = (const int*)d_in[11];
    const int*   io  = (const int*)d_in[12];
    float*       out = (float*)d_out;

    cudaFuncSetAttribute(model_kernel,
                         cudaFuncAttributeMaxDynamicSharedMemorySize, SMEM_BYTES);
    model_kernel<<<NROWS / RT, NTHR, SMEM_BYTES>>>(
        x, W1, b1, W2, b2, W3, b3, Wo, bo, i1, i2, i3, io, out);
}